// round 1
// baseline (speedup 1.0000x reference)
#include <cuda_runtime.h>
#include <math.h>

#define HEADS 16
#define GROUPS 4
#define BATCH 2
#define SEQ 2048
#define DM 2048
#define DKV 512
#define HD 128

// Scratch (allocation-free rule: __device__ globals)
__device__ float g_q[BATCH * SEQ * DM];
__device__ float g_k[BATCH * SEQ * DKV];
__device__ float g_v[BATCH * SEQ * DKV];

// ----------------------------------------------------------------------------
// GEMM: C[m,n] = sum_k A[m,k] * W[n,k]   (A: [M,K] rm, W: [N,K] rm, C: [M,N] rm)
// 128x128 block tile, Kt=8, 256 threads, 8x8 per-thread tile.
// ----------------------------------------------------------------------------
__global__ __launch_bounds__(256) void gemm_abt(const float* __restrict__ A,
                                                const float* __restrict__ W,
                                                float* __restrict__ C,
                                                int M, int N, int K) {
    __shared__ float As[8][128];
    __shared__ float Bs[8][128];

    const int tid = threadIdx.x;
    const int mBase = blockIdx.y * 128;
    const int nBase = blockIdx.x * 128;

    const int lrow = tid >> 1;          // 0..127
    const int lk   = (tid & 1) * 4;     // 0 or 4
    const int ty = tid >> 4;            // 0..15
    const int tx = tid & 15;            // 0..15

    float acc[8][8];
#pragma unroll
    for (int i = 0; i < 8; i++)
#pragma unroll
        for (int j = 0; j < 8; j++) acc[i][j] = 0.f;

    const float* aPtr = A + (mBase + lrow) * K + lk;
    const float* wPtr = W + (nBase + lrow) * K + lk;

    for (int k0 = 0; k0 < K; k0 += 8) {
        float4 av = *(const float4*)(aPtr + k0);
        float4 wv = *(const float4*)(wPtr + k0);
        __syncthreads();
        As[lk + 0][lrow] = av.x;
        As[lk + 1][lrow] = av.y;
        As[lk + 2][lrow] = av.z;
        As[lk + 3][lrow] = av.w;
        Bs[lk + 0][lrow] = wv.x;
        Bs[lk + 1][lrow] = wv.y;
        Bs[lk + 2][lrow] = wv.z;
        Bs[lk + 3][lrow] = wv.w;
        __syncthreads();
#pragma unroll
        for (int kk = 0; kk < 8; kk++) {
            float4 a0 = *(const float4*)&As[kk][ty * 8];
            float4 a1 = *(const float4*)&As[kk][ty * 8 + 4];
            float4 b0 = *(const float4*)&Bs[kk][tx * 8];
            float4 b1 = *(const float4*)&Bs[kk][tx * 8 + 4];
            float ar[8] = {a0.x, a0.y, a0.z, a0.w, a1.x, a1.y, a1.z, a1.w};
            float br[8] = {b0.x, b0.y, b0.z, b0.w, b1.x, b1.y, b1.z, b1.w};
#pragma unroll
            for (int i = 0; i < 8; i++)
#pragma unroll
                for (int j = 0; j < 8; j++) acc[i][j] += ar[i] * br[j];
        }
    }

#pragma unroll
    for (int i = 0; i < 8; i++) {
        float4 s0 = make_float4(acc[i][0], acc[i][1], acc[i][2], acc[i][3]);
        float4 s1 = make_float4(acc[i][4], acc[i][5], acc[i][6], acc[i][7]);
        float* cp = C + (mBase + ty * 8 + i) * N + nBase + tx * 8;
        *(float4*)cp = s0;
        *(float4*)(cp + 4) = s1;
    }
}

// ----------------------------------------------------------------------------
// Flash-style causal attention: Br=Bc=64, d=128.
// One CTA per (qtile, head, batch). 256 threads.
// smem: Qt[128][64] (k-major, scaled), Kt[128][64], Vs[64][128], St[64][65],
//       rowScale[64], rowInv[64]
// ----------------------------------------------------------------------------
#define ATTN_SMEM_FLOATS (8192 * 3 + 64 * 65 + 128)

__global__ __launch_bounds__(256) void attn_kernel(const float* __restrict__ q,
                                                   const float* __restrict__ k,
                                                   const float* __restrict__ v,
                                                   float* __restrict__ out) {
    extern __shared__ float sm[];
    float* Qt = sm;                 // [128][64]  Qt[d*64 + r]
    float* Kt = Qt + 8192;          // [128][64]  Kt[d*64 + c]
    float* Vs = Kt + 8192;          // [64][128]  Vs[j*128 + d]
    float* St = Vs + 8192;          // [64][65]   St[c*65 + r]  (S transposed)
    float* rowScale = St + 64 * 65; // [64]
    float* rowInv = rowScale + 64;  // [64]

    const int tid = threadIdx.x;
    const int qtile = blockIdx.x;
    const int h = blockIdx.y;
    const int b = blockIdx.z;
    const int g = h / (HEADS / GROUPS);
    const int qBase = qtile * 64;

    const float scale = 0.08838834764831845f; // 1/sqrt(128)

    // ---- Load Q tile transposed into Qt (scale folded in) ----
    {
        const int row = tid & 63;
        const int quarter = tid >> 6;
        const float* qp = q + (size_t)(b * SEQ + qBase + row) * DM + h * HD;
#pragma unroll
        for (int i = 0; i < 8; i++) {
            int k4 = quarter * 8 + i;           // 0..31
            float4 val = *(const float4*)(qp + k4 * 4);
            Qt[(k4 * 4 + 0) * 64 + row] = val.x * scale;
            Qt[(k4 * 4 + 1) * 64 + row] = val.y * scale;
            Qt[(k4 * 4 + 2) * 64 + row] = val.z * scale;
            Qt[(k4 * 4 + 3) * 64 + row] = val.w * scale;
        }
    }

    const int tr = tid >> 4;        // 0..15
    const int tc = tid & 15;        // 0..15
    const int r0 = tr * 4;          // phase A/C row base
    const int c0a = tc * 4;         // phase A col base
    const int c0c = tc * 8;         // phase C col base

    float m_r = -1e30f, l_r = 0.f;  // only meaningful for tid < 64
    float acc[4][8];
#pragma unroll
    for (int i = 0; i < 4; i++)
#pragma unroll
        for (int u = 0; u < 8; u++) acc[i][u] = 0.f;

    const int nkt = qtile + 1;
    for (int kt = 0; kt < nkt; kt++) {
        const int kBase = kt * 64;
        __syncthreads();  // previous phase-C done with Kt/Vs/St

        // ---- Load K transposed + V natural ----
        {
            const int row = tid & 63;
            const int quarter = tid >> 6;
            const float* kp = k + (size_t)(b * SEQ + kBase + row) * DKV + g * HD;
#pragma unroll
            for (int i = 0; i < 8; i++) {
                int k4 = quarter * 8 + i;
                float4 val = *(const float4*)(kp + k4 * 4);
                Kt[(k4 * 4 + 0) * 64 + row] = val.x;
                Kt[(k4 * 4 + 1) * 64 + row] = val.y;
                Kt[(k4 * 4 + 2) * 64 + row] = val.z;
                Kt[(k4 * 4 + 3) * 64 + row] = val.w;
            }
            const float* vp = v + (size_t)(b * SEQ + kBase) * DKV + g * HD;
#pragma unroll
            for (int i = 0; i < 8; i++) {
                int idx = tid + i * 256;        // float4 index 0..2047
                int vrow = idx >> 5;
                int vk4 = idx & 31;
                float4 val = *(const float4*)(vp + vrow * DKV + vk4 * 4);
                *(float4*)&Vs[vrow * 128 + vk4 * 4] = val;
            }
        }
        __syncthreads();

        // ---- Phase A: S = Q K^T  (4x4 per thread), store transposed ----
        float accs[4][4];
#pragma unroll
        for (int i = 0; i < 4; i++)
#pragma unroll
            for (int j = 0; j < 4; j++) accs[i][j] = 0.f;

#pragma unroll 4
        for (int d = 0; d < 128; d++) {
            float4 qv = *(const float4*)&Qt[d * 64 + r0];
            float4 kv = *(const float4*)&Kt[d * 64 + c0a];
            float qr[4] = {qv.x, qv.y, qv.z, qv.w};
            float kr[4] = {kv.x, kv.y, kv.z, kv.w};
#pragma unroll
            for (int i = 0; i < 4; i++)
#pragma unroll
                for (int j = 0; j < 4; j++) accs[i][j] += qr[i] * kr[j];
        }
        const bool diag = (kt == qtile);
#pragma unroll
        for (int i = 0; i < 4; i++)
#pragma unroll
            for (int j = 0; j < 4; j++) {
                float s = accs[i][j];
                if (diag && (c0a + j > r0 + i)) s = -1e30f;
                St[(c0a + j) * 65 + (r0 + i)] = s;
            }
        __syncthreads();

        // ---- Phase B: online softmax per row (tid < 64) ----
        if (tid < 64) {
            const int r = tid;
            float mx = m_r;
#pragma unroll 8
            for (int c = 0; c < 64; c++) mx = fmaxf(mx, St[c * 65 + r]);
            float sc = __expf(m_r - mx);
            float sum = 0.f;
#pragma unroll 8
            for (int c = 0; c < 64; c++) {
                float p = __expf(St[c * 65 + r] - mx);
                St[c * 65 + r] = p;
                sum += p;
            }
            l_r = l_r * sc + sum;
            m_r = mx;
            rowScale[r] = sc;
        }
        __syncthreads();

        // ---- Phase C: acc = acc*scale + P @ V  (4 rows x 8 cols per thread) ----
        float sc0 = rowScale[r0 + 0];
        float sc1 = rowScale[r0 + 1];
        float sc2 = rowScale[r0 + 2];
        float sc3 = rowScale[r0 + 3];
#pragma unroll
        for (int u = 0; u < 8; u++) {
            acc[0][u] *= sc0;
            acc[1][u] *= sc1;
            acc[2][u] *= sc2;
            acc[3][u] *= sc3;
        }
#pragma unroll 2
        for (int j = 0; j < 64; j++) {
            float p0 = St[j * 65 + r0 + 0];
            float p1 = St[j * 65 + r0 + 1];
            float p2 = St[j * 65 + r0 + 2];
            float p3 = St[j * 65 + r0 + 3];
            float4 v0 = *(const float4*)&Vs[j * 128 + c0c];
            float4 v1 = *(const float4*)&Vs[j * 128 + c0c + 4];
            float vr[8] = {v0.x, v0.y, v0.z, v0.w, v1.x, v1.y, v1.z, v1.w};
#pragma unroll
            for (int u = 0; u < 8; u++) {
                acc[0][u] += p0 * vr[u];
                acc[1][u] += p1 * vr[u];
                acc[2][u] += p2 * vr[u];
                acc[3][u] += p3 * vr[u];
            }
        }
    }

    __syncthreads();
    if (tid < 64) rowInv[tid] = 1.0f / l_r;
    __syncthreads();

    // ---- Write output: out[b, t, h*128 + c] ----
#pragma unroll
    for (int i = 0; i < 4; i++) {
        float inv = rowInv[r0 + i];
        float4 o0 = make_float4(acc[i][0] * inv, acc[i][1] * inv,
                                acc[i][2] * inv, acc[i][3] * inv);
        float4 o1 = make_float4(acc[i][4] * inv, acc[i][5] * inv,
                                acc[i][6] * inv, acc[i][7] * inv);
        float* op = out + (size_t)(b * SEQ + qBase + r0 + i) * DM + h * HD + c0c;
        *(float4*)op = o0;
        *(float4*)(op + 4) = o1;
    }
}

// ----------------------------------------------------------------------------
extern "C" void kernel_launch(void* const* d_in, const int* in_sizes, int n_in,
                              void* d_out, int out_size) {
    const float* x  = (const float*)d_in[0];
    const float* Wq = (const float*)d_in[1];
    const float* Wk = (const float*)d_in[2];
    const float* Wv = (const float*)d_in[3];
    float* out = (float*)d_out;

    float *pq = nullptr, *pk = nullptr, *pv = nullptr;
    cudaGetSymbolAddress((void**)&pq, g_q);
    cudaGetSymbolAddress((void**)&pk, g_k);
    cudaGetSymbolAddress((void**)&pv, g_v);

    const int M = BATCH * SEQ;   // 4096

    dim3 thr(256);
    dim3 gq(DM / 128, M / 128);
    gemm_abt<<<gq, thr>>>(x, Wq, pq, M, DM, DM);
    dim3 gk(DKV / 128, M / 128);
    gemm_abt<<<gk, thr>>>(x, Wk, pk, M, DKV, DM);
    gemm_abt<<<gk, thr>>>(x, Wv, pv, M, DKV, DM);

    static const size_t smemBytes = ATTN_SMEM_FLOATS * sizeof(float);
    cudaFuncSetAttribute(attn_kernel, cudaFuncAttributeMaxDynamicSharedMemorySize,
                         (int)smemBytes);
    dim3 ga(SEQ / 64, HEADS, BATCH);
    attn_kernel<<<ga, thr, smemBytes>>>(pq, pk, pv, out);
}

// round 2
// speedup vs baseline: 2.6092x; 2.6092x over previous
#include <cuda_runtime.h>
#include <math.h>

#define HEADS 16
#define GROUPS 4
#define BATCH 2
#define SEQ 2048
#define DM 2048
#define DKV 512
#define HD 128

// Scratch (allocation-free rule: __device__ globals)
__device__ float g_q[BATCH * SEQ * DM];
__device__ float g_k[BATCH * SEQ * DKV];
__device__ float g_v[BATCH * SEQ * DKV];

// ---------------------------------------------------------------------------
// helpers
// ---------------------------------------------------------------------------
__device__ __forceinline__ unsigned f2tf(float f) {
    unsigned u;
    asm("cvt.rna.tf32.f32 %0, %1;" : "=r"(u) : "f"(f));
    return u;
}

__device__ __forceinline__ void mma8(float c[4], const unsigned a[4],
                                     const unsigned b[2]) {
    asm volatile(
        "mma.sync.aligned.m16n8k8.row.col.f32.tf32.tf32.f32 "
        "{%0,%1,%2,%3}, {%4,%5,%6,%7}, {%8,%9}, {%0,%1,%2,%3};\n"
        : "+f"(c[0]), "+f"(c[1]), "+f"(c[2]), "+f"(c[3])
        : "r"(a[0]), "r"(a[1]), "r"(a[2]), "r"(a[3]), "r"(b[0]), "r"(b[1]));
}

// ---------------------------------------------------------------------------
// tf32 GEMM: C[m,n] = sum_k A[m,k] * W[n,k]
// A:[M,K] rm, W:[N,K] rm, C:[M,N] rm. 128x128x32 tile, 256 thr, 8 warps.
// Warp tile 64x32 (2x4 warp grid).
// ---------------------------------------------------------------------------
__global__ __launch_bounds__(256) void gemm_tf32(const float* __restrict__ A,
                                                 const float* __restrict__ W,
                                                 float* __restrict__ C,
                                                 int M, int N, int K) {
    __shared__ float As[128][36];
    __shared__ float Bs[128][36];

    const int tid = threadIdx.x;
    const int w = tid >> 5;
    const int lane = tid & 31;
    const int lg = lane >> 2;   // group 0..7
    const int t4 = lane & 3;    // 0..3
    const int wm = (w & 1) * 64;
    const int wn = (w >> 1) * 32;
    const int mBase = blockIdx.y * 128;
    const int nBase = blockIdx.x * 128;

    float acc[4][4][4];
#pragma unroll
    for (int mt = 0; mt < 4; mt++)
#pragma unroll
        for (int nt = 0; nt < 4; nt++)
#pragma unroll
            for (int i = 0; i < 4; i++) acc[mt][nt][i] = 0.f;

    // gmem load mapping: pass p: row p*32 + (tid>>3), col (tid&7)*4
    const int grow = tid >> 3;       // 0..31
    const int gcol = (tid & 7) * 4;  // 0..28

    const float* aPtr = A + (size_t)(mBase + grow) * K + gcol;
    const float* wPtr = W + (size_t)(nBase + grow) * K + gcol;

    float4 pa[4], pb[4];
#pragma unroll
    for (int p = 0; p < 4; p++) {
        pa[p] = *(const float4*)(aPtr + (size_t)p * 32 * K);
        pb[p] = *(const float4*)(wPtr + (size_t)p * 32 * K);
    }

    const int ktiles = K / 32;
    for (int kt = 0; kt < ktiles; kt++) {
#pragma unroll
        for (int p = 0; p < 4; p++) {
            float4 va = pa[p];
            float4 vb = pb[p];
            float4 ca = make_float4(__uint_as_float(f2tf(va.x)),
                                    __uint_as_float(f2tf(va.y)),
                                    __uint_as_float(f2tf(va.z)),
                                    __uint_as_float(f2tf(va.w)));
            float4 cb = make_float4(__uint_as_float(f2tf(vb.x)),
                                    __uint_as_float(f2tf(vb.y)),
                                    __uint_as_float(f2tf(vb.z)),
                                    __uint_as_float(f2tf(vb.w)));
            *(float4*)&As[p * 32 + grow][gcol] = ca;
            *(float4*)&Bs[p * 32 + grow][gcol] = cb;
        }
        __syncthreads();
        if (kt + 1 < ktiles) {
            const float* an = aPtr + (kt + 1) * 32;
            const float* wn2 = wPtr + (kt + 1) * 32;
#pragma unroll
            for (int p = 0; p < 4; p++) {
                pa[p] = *(const float4*)(an + (size_t)p * 32 * K);
                pb[p] = *(const float4*)(wn2 + (size_t)p * 32 * K);
            }
        }
#pragma unroll
        for (int ks = 0; ks < 4; ks++) {
            const int k0 = ks * 8;
            unsigned af[4][4];
#pragma unroll
            for (int mt = 0; mt < 4; mt++) {
                const int r = wm + mt * 16 + lg;
                af[mt][0] = __float_as_uint(As[r][k0 + t4]);
                af[mt][1] = __float_as_uint(As[r + 8][k0 + t4]);
                af[mt][2] = __float_as_uint(As[r][k0 + t4 + 4]);
                af[mt][3] = __float_as_uint(As[r + 8][k0 + t4 + 4]);
            }
#pragma unroll
            for (int nt = 0; nt < 4; nt++) {
                const int rn = wn + nt * 8 + lg;
                unsigned bf[2];
                bf[0] = __float_as_uint(Bs[rn][k0 + t4]);
                bf[1] = __float_as_uint(Bs[rn][k0 + t4 + 4]);
#pragma unroll
                for (int mt = 0; mt < 4; mt++) mma8(acc[mt][nt], af[mt], bf);
            }
        }
        __syncthreads();
    }

#pragma unroll
    for (int mt = 0; mt < 4; mt++)
#pragma unroll
        for (int nt = 0; nt < 4; nt++) {
            const int row = mBase + wm + mt * 16 + lg;
            const int col = nBase + wn + nt * 8 + 2 * t4;
            float2 v0 = make_float2(acc[mt][nt][0], acc[mt][nt][1]);
            float2 v1 = make_float2(acc[mt][nt][2], acc[mt][nt][3]);
            *(float2*)&C[(size_t)row * N + col] = v0;
            *(float2*)&C[(size_t)(row + 8) * N + col] = v1;
        }
}

// ---------------------------------------------------------------------------
// Flash attention with tf32 mma for QK^T and PV (as O^T = V^T P^T).
// Br=Bc=64, d=128. CTA per (qtile, head, batch). 256 thr, 8 warps.
// ---------------------------------------------------------------------------
#define LDQ 132
#define LDV 68
#define LDP 68
#define ATTN_SMEM_FLOATS (64 * LDQ * 2 + 128 * LDV + 64 * LDP + 128)

__global__ __launch_bounds__(256) void attn_tf32(const float* __restrict__ q,
                                                 const float* __restrict__ k,
                                                 const float* __restrict__ v,
                                                 float* __restrict__ out) {
    extern __shared__ float sm[];
    float* Qs = sm;                      // [64][132] row-major (tf32 bits)
    float* Ks = Qs + 64 * LDQ;           // [64][132]
    float* Vt = Ks + 64 * LDQ;           // [128][68]  Vt[d][j]
    float* St = Vt + 128 * LDV;          // [64][68]   S then P, row-major
    float* rowScale = St + 64 * LDP;     // [64]
    float* rowInv = rowScale + 64;       // [64]

    const int tid = threadIdx.x;
    const int w = tid >> 5;
    const int lane = tid & 31;
    const int lg = lane >> 2;
    const int t4 = lane & 3;

    const int qtile = blockIdx.x;
    const int h = blockIdx.y;
    const int b = blockIdx.z;
    const int grp = h / (HEADS / GROUPS);
    const int qBase = qtile * 64;

    const float scale = 0.08838834764831845f; // 1/sqrt(128)

    // phase A warp tile: 16(m) x 32(n)
    const int am = (w & 3) * 16;
    const int an = (w >> 2) * 32;
    // phase C warp tile: 16(d) x 64(r)
    const int wd = w * 16;

    // ---- load Q (scaled, tf32-rounded) ----
    {
        const int row = tid & 63;
        const int quarter = tid >> 6;
        const float* qp = q + (size_t)(b * SEQ + qBase + row) * DM + h * HD +
                          quarter * 32;
#pragma unroll
        for (int i = 0; i < 8; i++) {
            float4 val = *(const float4*)(qp + i * 4);
            float4 cv = make_float4(__uint_as_float(f2tf(val.x * scale)),
                                    __uint_as_float(f2tf(val.y * scale)),
                                    __uint_as_float(f2tf(val.z * scale)),
                                    __uint_as_float(f2tf(val.w * scale)));
            *(float4*)&Qs[row * LDQ + quarter * 32 + i * 4] = cv;
        }
    }

    // softmax state: 4 threads per row keep identical copies
    float m_r = -1e30f, l_r = 0.f;
    const int srow = tid >> 2;       // 0..63
    const int sq = tid & 3;          // quarter of columns

    // O^T accumulators: 8 n-tiles x 4
    float oacc[8][4];
#pragma unroll
    for (int nt = 0; nt < 8; nt++)
#pragma unroll
        for (int i = 0; i < 4; i++) oacc[nt][i] = 0.f;

    const int nkt = qtile + 1;
    for (int kt = 0; kt < nkt; kt++) {
        const int kBase = kt * 64;
        __syncthreads();  // prev iter done with Ks/Vt/St

        // ---- load K row-major, V transposed ----
        {
            const int row = tid & 63;
            const int quarter = tid >> 6;
            const float* kp = k + (size_t)(b * SEQ + kBase + row) * DKV +
                              grp * HD + quarter * 32;
#pragma unroll
            for (int i = 0; i < 8; i++) {
                float4 val = *(const float4*)(kp + i * 4);
                float4 cv = make_float4(__uint_as_float(f2tf(val.x)),
                                        __uint_as_float(f2tf(val.y)),
                                        __uint_as_float(f2tf(val.z)),
                                        __uint_as_float(f2tf(val.w)));
                *(float4*)&Ks[row * LDQ + quarter * 32 + i * 4] = cv;
            }
            const float* vp = v + (size_t)(b * SEQ + kBase + row) * DKV +
                              grp * HD + quarter * 32;
#pragma unroll
            for (int i = 0; i < 8; i++) {
                float4 val = *(const float4*)(vp + i * 4);
                const int c = quarter * 32 + i * 4;
                Vt[(c + 0) * LDV + row] = __uint_as_float(f2tf(val.x));
                Vt[(c + 1) * LDV + row] = __uint_as_float(f2tf(val.y));
                Vt[(c + 2) * LDV + row] = __uint_as_float(f2tf(val.z));
                Vt[(c + 3) * LDV + row] = __uint_as_float(f2tf(val.w));
            }
        }
        __syncthreads();

        // ---- phase A: S = Q K^T ----
        float sacc[4][4];
#pragma unroll
        for (int nt = 0; nt < 4; nt++)
#pragma unroll
            for (int i = 0; i < 4; i++) sacc[nt][i] = 0.f;

#pragma unroll
        for (int ks = 0; ks < 16; ks++) {
            const int k0 = ks * 8;
            unsigned af[4];
            const int ar = am + lg;
            af[0] = __float_as_uint(Qs[ar * LDQ + k0 + t4]);
            af[1] = __float_as_uint(Qs[(ar + 8) * LDQ + k0 + t4]);
            af[2] = __float_as_uint(Qs[ar * LDQ + k0 + t4 + 4]);
            af[3] = __float_as_uint(Qs[(ar + 8) * LDQ + k0 + t4 + 4]);
#pragma unroll
            for (int nt = 0; nt < 4; nt++) {
                const int br = an + nt * 8 + lg;
                unsigned bf[2];
                bf[0] = __float_as_uint(Ks[br * LDQ + k0 + t4]);
                bf[1] = __float_as_uint(Ks[br * LDQ + k0 + t4 + 4]);
                mma8(sacc[nt], af, bf);
            }
        }
        // mask + store S row-major
        const bool diag = (kt == qtile);
#pragma unroll
        for (int nt = 0; nt < 4; nt++) {
            const int i0 = am + lg;
            const int j0 = an + nt * 8 + 2 * t4;
            float s00 = sacc[nt][0], s01 = sacc[nt][1];
            float s10 = sacc[nt][2], s11 = sacc[nt][3];
            if (diag) {
                if (j0 > i0) s00 = -1e30f;
                if (j0 + 1 > i0) s01 = -1e30f;
                if (j0 > i0 + 8) s10 = -1e30f;
                if (j0 + 1 > i0 + 8) s11 = -1e30f;
            }
            *(float2*)&St[i0 * LDP + j0] = make_float2(s00, s01);
            *(float2*)&St[(i0 + 8) * LDP + j0] = make_float2(s10, s11);
        }
        __syncthreads();

        // ---- phase B: online softmax (4 threads per row) ----
        {
            float* sp = &St[srow * LDP + sq * 16];
            float mxl = -1e30f;
#pragma unroll
            for (int c = 0; c < 16; c++) mxl = fmaxf(mxl, sp[c]);
            mxl = fmaxf(mxl, __shfl_xor_sync(0xffffffff, mxl, 1));
            mxl = fmaxf(mxl, __shfl_xor_sync(0xffffffff, mxl, 2));
            const float mnew = fmaxf(m_r, mxl);
            const float sc = __expf(m_r - mnew);
            float sum = 0.f;
#pragma unroll
            for (int c = 0; c < 16; c++) {
                float p = __expf(sp[c] - mnew);
                sp[c] = p;
                sum += p;
            }
            sum += __shfl_xor_sync(0xffffffff, sum, 1);
            sum += __shfl_xor_sync(0xffffffff, sum, 2);
            l_r = l_r * sc + sum;
            m_r = mnew;
            if (sq == 0) rowScale[srow] = sc;
        }
        __syncthreads();

        // ---- phase C: O^T = V^T P^T (accumulate) ----
#pragma unroll
        for (int nt = 0; nt < 8; nt++) {
            const int r0 = nt * 8 + 2 * t4;
            float2 scv = *(const float2*)&rowScale[r0];
            oacc[nt][0] *= scv.x;
            oacc[nt][1] *= scv.y;
            oacc[nt][2] *= scv.x;
            oacc[nt][3] *= scv.y;
        }
#pragma unroll
        for (int ks = 0; ks < 8; ks++) {
            const int j0 = ks * 8;
            unsigned af[4];
            const int vr = wd + lg;
            af[0] = __float_as_uint(Vt[vr * LDV + j0 + t4]);
            af[1] = __float_as_uint(Vt[(vr + 8) * LDV + j0 + t4]);
            af[2] = __float_as_uint(Vt[vr * LDV + j0 + t4 + 4]);
            af[3] = __float_as_uint(Vt[(vr + 8) * LDV + j0 + t4 + 4]);
#pragma unroll
            for (int nt = 0; nt < 8; nt++) {
                const int pr = nt * 8 + lg;
                unsigned bf[2];
                bf[0] = __float_as_uint(St[pr * LDP + j0 + t4]);
                bf[1] = __float_as_uint(St[pr * LDP + j0 + t4 + 4]);
                mma8(oacc[nt], af, bf);
            }
        }
    }

    // ---- finalize ----
    if (sq == 0) rowInv[srow] = 1.0f / l_r;
    __syncthreads();

#pragma unroll
    for (int nt = 0; nt < 8; nt++) {
        const int r0 = nt * 8 + 2 * t4;
        float2 inv = *(const float2*)&rowInv[r0];
        const int d0 = wd + lg;
        float* o0 = out + (size_t)(b * SEQ + qBase + r0) * DM + h * HD;
        float* o1 = out + (size_t)(b * SEQ + qBase + r0 + 1) * DM + h * HD;
        o0[d0] = oacc[nt][0] * inv.x;
        o1[d0] = oacc[nt][1] * inv.y;
        o0[d0 + 8] = oacc[nt][2] * inv.x;
        o1[d0 + 8] = oacc[nt][3] * inv.y;
    }
}

// ---------------------------------------------------------------------------
extern "C" void kernel_launch(void* const* d_in, const int* in_sizes, int n_in,
                              void* d_out, int out_size) {
    const float* x = (const float*)d_in[0];
    const float* Wq = (const float*)d_in[1];
    const float* Wk = (const float*)d_in[2];
    const float* Wv = (const float*)d_in[3];
    float* out = (float*)d_out;

    float *pq = nullptr, *pk = nullptr, *pv = nullptr;
    cudaGetSymbolAddress((void**)&pq, g_q);
    cudaGetSymbolAddress((void**)&pk, g_k);
    cudaGetSymbolAddress((void**)&pv, g_v);

    const int M = BATCH * SEQ; // 4096

    dim3 thr(256);
    dim3 gq(DM / 128, M / 128);
    gemm_tf32<<<gq, thr>>>(x, Wq, pq, M, DM, DM);
    dim3 gk(DKV / 128, M / 128);
    gemm_tf32<<<gk, thr>>>(x, Wk, pk, M, DKV, DM);
    gemm_tf32<<<gk, thr>>>(x, Wv, pv, M, DKV, DM);

    static const size_t smemBytes = ATTN_SMEM_FLOATS * sizeof(float);
    cudaFuncSetAttribute(attn_tf32, cudaFuncAttributeMaxDynamicSharedMemorySize,
                         (int)smemBytes);
    dim3 ga(SEQ / 64, HEADS, BATCH);
    attn_tf32<<<ga, thr, smemBytes>>>(pq, pk, pv, out);
}

// round 3
// speedup vs baseline: 4.0028x; 1.5341x over previous
#include <cuda_runtime.h>
#include <math.h>

#define HEADS 16
#define GROUPS 4
#define BATCH 2
#define SEQ 2048
#define DM 2048
#define DKV 512
#define HD 128

// Scratch (allocation-free rule: __device__ globals)
__device__ float g_q[BATCH * SEQ * DM];
__device__ float g_k[BATCH * SEQ * DKV];
__device__ float g_v[BATCH * SEQ * DKV];

// ---------------------------------------------------------------------------
// helpers
// ---------------------------------------------------------------------------
__device__ __forceinline__ unsigned f2tf(float f) {
    unsigned u;
    asm("cvt.rna.tf32.f32 %0, %1;" : "=r"(u) : "f"(f));
    return u;
}

__device__ __forceinline__ float fexp2(float x) {
    float r;
    asm("ex2.approx.f32 %0, %1;" : "=f"(r) : "f"(x));
    return r;
}

__device__ __forceinline__ void mma8(float c[4], const unsigned a[4],
                                     const unsigned b[2]) {
    asm volatile(
        "mma.sync.aligned.m16n8k8.row.col.f32.tf32.tf32.f32 "
        "{%0,%1,%2,%3}, {%4,%5,%6,%7}, {%8,%9}, {%0,%1,%2,%3};\n"
        : "+f"(c[0]), "+f"(c[1]), "+f"(c[2]), "+f"(c[3])
        : "r"(a[0]), "r"(a[1]), "r"(a[2]), "r"(a[3]), "r"(b[0]), "r"(b[1]));
}

// ---------------------------------------------------------------------------
// tf32 GEMM: C[m,n] = sum_k A[m,k] * W[n,k]  (unchanged from round 2)
// ---------------------------------------------------------------------------
__global__ __launch_bounds__(256) void gemm_tf32(const float* __restrict__ A,
                                                 const float* __restrict__ W,
                                                 float* __restrict__ C,
                                                 int M, int N, int K) {
    __shared__ float As[128][36];
    __shared__ float Bs[128][36];

    const int tid = threadIdx.x;
    const int w = tid >> 5;
    const int lane = tid & 31;
    const int lg = lane >> 2;
    const int t4 = lane & 3;
    const int wm = (w & 1) * 64;
    const int wn = (w >> 1) * 32;
    const int mBase = blockIdx.y * 128;
    const int nBase = blockIdx.x * 128;

    float acc[4][4][4];
#pragma unroll
    for (int mt = 0; mt < 4; mt++)
#pragma unroll
        for (int nt = 0; nt < 4; nt++)
#pragma unroll
            for (int i = 0; i < 4; i++) acc[mt][nt][i] = 0.f;

    const int grow = tid >> 3;
    const int gcol = (tid & 7) * 4;

    const float* aPtr = A + (size_t)(mBase + grow) * K + gcol;
    const float* wPtr = W + (size_t)(nBase + grow) * K + gcol;

    float4 pa[4], pb[4];
#pragma unroll
    for (int p = 0; p < 4; p++) {
        pa[p] = *(const float4*)(aPtr + (size_t)p * 32 * K);
        pb[p] = *(const float4*)(wPtr + (size_t)p * 32 * K);
    }

    const int ktiles = K / 32;
    for (int kt = 0; kt < ktiles; kt++) {
#pragma unroll
        for (int p = 0; p < 4; p++) {
            float4 va = pa[p];
            float4 vb = pb[p];
            float4 ca = make_float4(__uint_as_float(f2tf(va.x)),
                                    __uint_as_float(f2tf(va.y)),
                                    __uint_as_float(f2tf(va.z)),
                                    __uint_as_float(f2tf(va.w)));
            float4 cb = make_float4(__uint_as_float(f2tf(vb.x)),
                                    __uint_as_float(f2tf(vb.y)),
                                    __uint_as_float(f2tf(vb.z)),
                                    __uint_as_float(f2tf(vb.w)));
            *(float4*)&As[p * 32 + grow][gcol] = ca;
            *(float4*)&Bs[p * 32 + grow][gcol] = cb;
        }
        __syncthreads();
        if (kt + 1 < ktiles) {
            const float* an = aPtr + (kt + 1) * 32;
            const float* wn2 = wPtr + (kt + 1) * 32;
#pragma unroll
            for (int p = 0; p < 4; p++) {
                pa[p] = *(const float4*)(an + (size_t)p * 32 * K);
                pb[p] = *(const float4*)(wn2 + (size_t)p * 32 * K);
            }
        }
#pragma unroll
        for (int ks = 0; ks < 4; ks++) {
            const int k0 = ks * 8;
            unsigned af[4][4];
#pragma unroll
            for (int mt = 0; mt < 4; mt++) {
                const int r = wm + mt * 16 + lg;
                af[mt][0] = __float_as_uint(As[r][k0 + t4]);
                af[mt][1] = __float_as_uint(As[r + 8][k0 + t4]);
                af[mt][2] = __float_as_uint(As[r][k0 + t4 + 4]);
                af[mt][3] = __float_as_uint(As[r + 8][k0 + t4 + 4]);
            }
#pragma unroll
            for (int nt = 0; nt < 4; nt++) {
                const int rn = wn + nt * 8 + lg;
                unsigned bf[2];
                bf[0] = __float_as_uint(Bs[rn][k0 + t4]);
                bf[1] = __float_as_uint(Bs[rn][k0 + t4 + 4]);
#pragma unroll
                for (int mt = 0; mt < 4; mt++) mma8(acc[mt][nt], af[mt], bf);
            }
        }
        __syncthreads();
    }

#pragma unroll
    for (int mt = 0; mt < 4; mt++)
#pragma unroll
        for (int nt = 0; nt < 4; nt++) {
            const int row = mBase + wm + mt * 16 + lg;
            const int col = nBase + wn + nt * 8 + 2 * t4;
            float2 v0 = make_float2(acc[mt][nt][0], acc[mt][nt][1]);
            float2 v1 = make_float2(acc[mt][nt][2], acc[mt][nt][3]);
            *(float2*)&C[(size_t)row * N + col] = v0;
            *(float2*)&C[(size_t)(row + 8) * N + col] = v1;
        }
}

// ---------------------------------------------------------------------------
// Register-resident flash attention. Br=128, Bc=64, 8 warps.
// Q fragments in registers; S/softmax/P in registers (quad shfls);
// only K and V pass through smem. 2 barriers per kt-iter.
// ---------------------------------------------------------------------------
#define BQ 128
#define BK 64
#define LDK 132
#define LDV 136
#define LDQS 132
#define ATTN_SMEM_FLOATS (BK * LDK + BK * LDV)  // 17152 > BQ*LDQS=16896

__global__ __launch_bounds__(256, 1) void attn_mma(const float* __restrict__ q,
                                                   const float* __restrict__ k,
                                                   const float* __restrict__ v,
                                                   float* __restrict__ out) {
    extern __shared__ float sm[];
    float* Ks = sm;                 // [BK][LDK]
    float* Vs = sm + BK * LDK;      // [BK][LDV]
    float* Qstage = sm;             // [BQ][LDQS] overlay (pre-loop only)

    const int tid = threadIdx.x;
    const int w = tid >> 5;
    const int lane = tid & 31;
    const int lg = lane >> 2;
    const int t4 = lane & 3;

    const int qt = gridDim.x - 1 - blockIdx.x;   // heavy tiles first
    const int h = blockIdx.y;
    const int b = blockIdx.z;
    const int grp = h / (HEADS / GROUPS);
    const int qBase = qt * BQ;
    const int wq0 = w * 16;

    // 1/sqrt(128) * log2(e): softmax done in base-2 domain
    const float qscale = 0.08838834764831845f * 1.4426950408889634f;

    // ---- stage Q (scaled + tf32) then pull fragments to registers ----
#pragma unroll
    for (int rnd = 0; rnd < 16; rnd++) {
        const int row = (tid >> 5) + rnd * 8;
        const float* qp = q + (size_t)(b * SEQ + qBase + row) * DM + h * HD +
                          lane * 4;
        float4 val = *(const float4*)qp;
        float4 cv = make_float4(__uint_as_float(f2tf(val.x * qscale)),
                                __uint_as_float(f2tf(val.y * qscale)),
                                __uint_as_float(f2tf(val.z * qscale)),
                                __uint_as_float(f2tf(val.w * qscale)));
        *(float4*)&Qstage[row * LDQS + lane * 4] = cv;
    }
    __syncthreads();

    unsigned qf[16][4];
    {
        const int r = wq0 + lg;
#pragma unroll
        for (int ks = 0; ks < 16; ks++) {
            qf[ks][0] = __float_as_uint(Qstage[r * LDQS + ks * 8 + t4]);
            qf[ks][1] = __float_as_uint(Qstage[(r + 8) * LDQS + ks * 8 + t4]);
            qf[ks][2] = __float_as_uint(Qstage[r * LDQS + ks * 8 + t4 + 4]);
            qf[ks][3] = __float_as_uint(Qstage[(r + 8) * LDQS + ks * 8 + t4 + 4]);
        }
    }
    // loop-top barrier of iter 0 protects Qstage before K/V overwrite

    float oacc[16][4];
#pragma unroll
    for (int nt = 0; nt < 16; nt++)
#pragma unroll
        for (int i = 0; i < 4; i++) oacc[nt][i] = 0.f;

    float m0 = -1e30f, m1 = -1e30f, l0 = 0.f, l1 = 0.f;
    const int lastRow = qBase + wq0 + 15;
    const int row0g = qBase + wq0 + lg;
    const int nkt = (qBase + BQ) / BK;   // 2*qt + 2

    for (int kt = 0; kt < nkt; kt++) {
        const int kBase = kt * BK;
        __syncthreads();   // previous iter's fragment reads complete

        // ---- cooperative K/V tile load (fp32 -> tf32 bits) ----
#pragma unroll
        for (int rnd = 0; rnd < 8; rnd++) {
            const int row = (tid >> 5) + rnd * 8;
            const size_t base = (size_t)(b * SEQ + kBase + row) * DKV +
                                grp * HD + lane * 4;
            float4 kv4 = *(const float4*)(k + base);
            float4 ck = make_float4(__uint_as_float(f2tf(kv4.x)),
                                    __uint_as_float(f2tf(kv4.y)),
                                    __uint_as_float(f2tf(kv4.z)),
                                    __uint_as_float(f2tf(kv4.w)));
            *(float4*)&Ks[row * LDK + lane * 4] = ck;
            float4 vv4 = *(const float4*)(v + base);
            float4 cvv = make_float4(__uint_as_float(f2tf(vv4.x)),
                                     __uint_as_float(f2tf(vv4.y)),
                                     __uint_as_float(f2tf(vv4.z)),
                                     __uint_as_float(f2tf(vv4.w)));
            *(float4*)&Vs[row * LDV + lane * 4] = cvv;
        }
        __syncthreads();

        if (kBase > lastRow) continue;   // warp-uniform; barrier counts match

        // ---- phase A: S = Q K^T (registers) ----
        float sacc[8][4];
#pragma unroll
        for (int nt = 0; nt < 8; nt++)
#pragma unroll
            for (int i = 0; i < 4; i++) sacc[nt][i] = 0.f;

#pragma unroll
        for (int ks = 0; ks < 16; ks++) {
            const int k0 = ks * 8;
#pragma unroll
            for (int nt = 0; nt < 8; nt++) {
                unsigned bf[2];
                const float* kp = &Ks[(nt * 8 + lg) * LDK + k0 + t4];
                bf[0] = __float_as_uint(kp[0]);
                bf[1] = __float_as_uint(kp[4]);
                mma8(sacc[nt], qf[ks], bf);
            }
        }

        // ---- causal mask ----
        if (kBase + BK - 1 > qBase + wq0) {
#pragma unroll
            for (int nt = 0; nt < 8; nt++) {
                const int c0 = kBase + nt * 8 + 2 * t4;
                if (c0 > row0g) sacc[nt][0] = -1e30f;
                if (c0 + 1 > row0g) sacc[nt][1] = -1e30f;
                if (c0 > row0g + 8) sacc[nt][2] = -1e30f;
                if (c0 + 1 > row0g + 8) sacc[nt][3] = -1e30f;
            }
        }

        // ---- online softmax (base-2), all in registers + quad shfl ----
        float mx0 = -1e30f, mx1 = -1e30f;
#pragma unroll
        for (int nt = 0; nt < 8; nt++) {
            mx0 = fmaxf(mx0, fmaxf(sacc[nt][0], sacc[nt][1]));
            mx1 = fmaxf(mx1, fmaxf(sacc[nt][2], sacc[nt][3]));
        }
        mx0 = fmaxf(mx0, __shfl_xor_sync(0xffffffff, mx0, 1));
        mx0 = fmaxf(mx0, __shfl_xor_sync(0xffffffff, mx0, 2));
        mx1 = fmaxf(mx1, __shfl_xor_sync(0xffffffff, mx1, 1));
        mx1 = fmaxf(mx1, __shfl_xor_sync(0xffffffff, mx1, 2));

        const float mn0 = fmaxf(m0, mx0);
        const float mn1 = fmaxf(m1, mx1);
        const float sc0 = fexp2(m0 - mn0);
        const float sc1 = fexp2(m1 - mn1);

        float sum0 = 0.f, sum1 = 0.f;
#pragma unroll
        for (int nt = 0; nt < 8; nt++) {
            float p0 = fexp2(sacc[nt][0] - mn0);
            float p1 = fexp2(sacc[nt][1] - mn0);
            float p2 = fexp2(sacc[nt][2] - mn1);
            float p3 = fexp2(sacc[nt][3] - mn1);
            sacc[nt][0] = p0; sacc[nt][1] = p1;
            sacc[nt][2] = p2; sacc[nt][3] = p3;
            sum0 += p0 + p1;
            sum1 += p2 + p3;
        }
        sum0 += __shfl_xor_sync(0xffffffff, sum0, 1);
        sum0 += __shfl_xor_sync(0xffffffff, sum0, 2);
        sum1 += __shfl_xor_sync(0xffffffff, sum1, 1);
        sum1 += __shfl_xor_sync(0xffffffff, sum1, 2);

        l0 = l0 * sc0 + sum0;  m0 = mn0;
        l1 = l1 * sc1 + sum1;  m1 = mn1;

#pragma unroll
        for (int nt = 0; nt < 16; nt++) {
            oacc[nt][0] *= sc0;
            oacc[nt][1] *= sc0;
            oacc[nt][2] *= sc1;
            oacc[nt][3] *= sc1;
        }

        // ---- phase C: O += P V ; P re-shaped C-frag -> A-frag via shfl ----
        const int srcA = (lane & 28) | (t4 >> 1);
        const int srcB = srcA + 2;
        const bool odd = (t4 & 1);
#pragma unroll
        for (int ks = 0; ks < 8; ks++) {
            const float v0 = sacc[ks][0], v1 = sacc[ks][1];
            const float v2 = sacc[ks][2], v3 = sacc[ks][3];
            float x0 = __shfl_sync(0xffffffff, v0, srcA);
            float x1 = __shfl_sync(0xffffffff, v1, srcA);
            float y0 = __shfl_sync(0xffffffff, v0, srcB);
            float y1 = __shfl_sync(0xffffffff, v1, srcB);
            float z0 = __shfl_sync(0xffffffff, v2, srcA);
            float z1 = __shfl_sync(0xffffffff, v3, srcA);
            float u0 = __shfl_sync(0xffffffff, v2, srcB);
            float u1 = __shfl_sync(0xffffffff, v3, srcB);
            unsigned pf[4];
            pf[0] = f2tf(odd ? x1 : x0);   // P[lg][k0+t4]
            pf[1] = f2tf(odd ? z1 : z0);   // P[lg+8][k0+t4]
            pf[2] = f2tf(odd ? y1 : y0);   // P[lg][k0+t4+4]
            pf[3] = f2tf(odd ? u1 : u0);   // P[lg+8][k0+t4+4]

            const int k0 = ks * 8;
#pragma unroll
            for (int nt = 0; nt < 16; nt++) {
                unsigned bf[2];
                bf[0] = __float_as_uint(Vs[(k0 + t4) * LDV + nt * 8 + lg]);
                bf[1] = __float_as_uint(Vs[(k0 + t4 + 4) * LDV + nt * 8 + lg]);
                mma8(oacc[nt], pf, bf);
            }
        }
    }

    // ---- finalize + write ----
    const float inv0 = 1.0f / l0;
    const float inv1 = 1.0f / l1;
#pragma unroll
    for (int nt = 0; nt < 16; nt++) {
        const int d = h * HD + nt * 8 + 2 * t4;
        float2 w0 = make_float2(oacc[nt][0] * inv0, oacc[nt][1] * inv0);
        float2 w1 = make_float2(oacc[nt][2] * inv1, oacc[nt][3] * inv1);
        *(float2*)&out[(size_t)(b * SEQ + row0g) * DM + d] = w0;
        *(float2*)&out[(size_t)(b * SEQ + row0g + 8) * DM + d] = w1;
    }
}

// ---------------------------------------------------------------------------
extern "C" void kernel_launch(void* const* d_in, const int* in_sizes, int n_in,
                              void* d_out, int out_size) {
    const float* x = (const float*)d_in[0];
    const float* Wq = (const float*)d_in[1];
    const float* Wk = (const float*)d_in[2];
    const float* Wv = (const float*)d_in[3];
    float* out = (float*)d_out;

    float *pq = nullptr, *pk = nullptr, *pv = nullptr;
    cudaGetSymbolAddress((void**)&pq, g_q);
    cudaGetSymbolAddress((void**)&pk, g_k);
    cudaGetSymbolAddress((void**)&pv, g_v);

    const int M = BATCH * SEQ; // 4096

    dim3 thr(256);
    dim3 gq(DM / 128, M / 128);
    gemm_tf32<<<gq, thr>>>(x, Wq, pq, M, DM, DM);
    dim3 gk(DKV / 128, M / 128);
    gemm_tf32<<<gk, thr>>>(x, Wk, pk, M, DKV, DM);
    gemm_tf32<<<gk, thr>>>(x, Wv, pv, M, DKV, DM);

    static const size_t smemBytes = ATTN_SMEM_FLOATS * sizeof(float);
    cudaFuncSetAttribute(attn_mma, cudaFuncAttributeMaxDynamicSharedMemorySize,
                         (int)smemBytes);
    dim3 ga(SEQ / BQ, HEADS, BATCH);
    attn_mma<<<ga, thr, smemBytes>>>(pq, pk, pv, out);
}

// round 4
// speedup vs baseline: 4.9500x; 1.2366x over previous
#include <cuda_runtime.h>
#include <math.h>

#define HEADS 16
#define GROUPS 4
#define BATCH 2
#define SEQ 2048
#define DM 2048
#define DKV 512
#define HD 128
#define KD 2048

// Scratch (allocation-free rule: __device__ globals)
__device__ float g_q[BATCH * SEQ * DM];
__device__ float g_k[BATCH * SEQ * DKV];
__device__ float g_v[BATCH * SEQ * DKV];

// ---------------------------------------------------------------------------
// helpers
// ---------------------------------------------------------------------------
__device__ __forceinline__ unsigned f2tf(float f) {
    unsigned u;
    asm("cvt.rna.tf32.f32 %0, %1;" : "=r"(u) : "f"(f));
    return u;
}

__device__ __forceinline__ float fexp2(float x) {
    float r;
    asm("ex2.approx.f32 %0, %1;" : "=f"(r) : "f"(x));
    return r;
}

__device__ __forceinline__ void mma8(float c[4], const unsigned a[4],
                                     const unsigned b[2]) {
    asm volatile(
        "mma.sync.aligned.m16n8k8.row.col.f32.tf32.tf32.f32 "
        "{%0,%1,%2,%3}, {%4,%5,%6,%7}, {%8,%9}, {%0,%1,%2,%3};\n"
        : "+f"(c[0]), "+f"(c[1]), "+f"(c[2]), "+f"(c[3])
        : "r"(a[0]), "r"(a[1]), "r"(a[2]), "r"(a[3]), "r"(b[0]), "r"(b[1]));
}

__device__ __forceinline__ void ldmx4(unsigned r[4], const float* p) {
    unsigned addr = (unsigned)__cvta_generic_to_shared(p);
    asm volatile(
        "ldmatrix.sync.aligned.m8n8.x4.shared.b16 {%0,%1,%2,%3}, [%4];"
        : "=r"(r[0]), "=r"(r[1]), "=r"(r[2]), "=r"(r[3])
        : "r"(addr));
}

// ---------------------------------------------------------------------------
// Fused QKV projection GEMM.
// C[m,n] = sum_k x[m,k] * W[n,k] over concatenated N = 2048(Q)+512(K)+512(V).
// CTA tile 128(m) x 256(n) x 32(k), 8 warps (2m x 4n grid), warp tile 64x64.
// Fragments via ldmatrix.x4.
// ---------------------------------------------------------------------------
#define GLDA 36
#define GEMM_SMEM_FLOATS (128 * GLDA + 256 * GLDA)

__global__ __launch_bounds__(256) void gemm_qkv(const float* __restrict__ x,
                                                const float* __restrict__ Wq,
                                                const float* __restrict__ Wk,
                                                const float* __restrict__ Wv) {
    extern __shared__ float gsm[];
    float* As = gsm;                  // [128][GLDA]
    float* Bs = gsm + 128 * GLDA;     // [256][GLDA]

    const int tid = threadIdx.x;
    const int w = tid >> 5;
    const int lane = tid & 31;
    const int lg = lane >> 2;
    const int t4 = lane & 3;
    const int wm = (w & 1) * 64;
    const int wn = (w >> 1) * 64;
    const int mBase = blockIdx.y * 128;
    const int nb = blockIdx.x;        // 0..11

    const float* W;
    float* C;
    int cN, nl0;
    if (nb < 8)       { W = Wq; C = g_q; cN = DM;  nl0 = nb * 256; }
    else if (nb < 10) { W = Wk; C = g_k; cN = DKV; nl0 = (nb - 8) * 256; }
    else              { W = Wv; C = g_v; cN = DKV; nl0 = (nb - 10) * 256; }

    float acc[4][8][4];
#pragma unroll
    for (int mt = 0; mt < 4; mt++)
#pragma unroll
        for (int nt = 0; nt < 8; nt++)
#pragma unroll
            for (int i = 0; i < 4; i++) acc[mt][nt][i] = 0.f;

    const int grow = tid >> 3;        // 0..31
    const int gcol = (tid & 7) * 4;   // 0..28

    const float* ap = x + (size_t)(mBase + grow) * KD + gcol;
    const float* wp = W + (size_t)(nl0 + grow) * KD + gcol;

    // fragment smem addresses (constant per thread)
    const int aRow = wm + ((lane >> 3) & 1) * 8 + (lane & 7);
    const int aCol = (lane >> 4) * 4;
    const int bRow = wn + ((lane >> 4) & 1) * 8 + (lane & 7);
    const int bCol = ((lane >> 3) & 1) * 4;

    float4 pa[4], pb[8];
#pragma unroll
    for (int p = 0; p < 4; p++) pa[p] = *(const float4*)(ap + (size_t)p * 32 * KD);
#pragma unroll
    for (int p = 0; p < 8; p++) pb[p] = *(const float4*)(wp + (size_t)p * 32 * KD);

    const int ktiles = KD / 32;
    for (int kt = 0; kt < ktiles; kt++) {
#pragma unroll
        for (int p = 0; p < 4; p++) {
            float4 va = pa[p];
            *(float4*)&As[(p * 32 + grow) * GLDA + gcol] =
                make_float4(__uint_as_float(f2tf(va.x)), __uint_as_float(f2tf(va.y)),
                            __uint_as_float(f2tf(va.z)), __uint_as_float(f2tf(va.w)));
        }
#pragma unroll
        for (int p = 0; p < 8; p++) {
            float4 vb = pb[p];
            *(float4*)&Bs[(p * 32 + grow) * GLDA + gcol] =
                make_float4(__uint_as_float(f2tf(vb.x)), __uint_as_float(f2tf(vb.y)),
                            __uint_as_float(f2tf(vb.z)), __uint_as_float(f2tf(vb.w)));
        }
        __syncthreads();
        if (kt + 1 < ktiles) {
            const float* an = ap + (kt + 1) * 32;
            const float* wn2 = wp + (kt + 1) * 32;
#pragma unroll
            for (int p = 0; p < 4; p++)
                pa[p] = *(const float4*)(an + (size_t)p * 32 * KD);
#pragma unroll
            for (int p = 0; p < 8; p++)
                pb[p] = *(const float4*)(wn2 + (size_t)p * 32 * KD);
        }
#pragma unroll
        for (int ks = 0; ks < 4; ks++) {
            const int k0 = ks * 8;
            unsigned af[4][4], bf[4][4];
#pragma unroll
            for (int mt = 0; mt < 4; mt++)
                ldmx4(af[mt], &As[(aRow + mt * 16) * GLDA + k0 + aCol]);
#pragma unroll
            for (int ntp = 0; ntp < 4; ntp++)
                ldmx4(bf[ntp], &Bs[(bRow + ntp * 16) * GLDA + k0 + bCol]);
#pragma unroll
            for (int mt = 0; mt < 4; mt++)
#pragma unroll
                for (int nt = 0; nt < 8; nt++)
                    mma8(acc[mt][nt], af[mt], &bf[nt >> 1][(nt & 1) * 2]);
        }
        __syncthreads();
    }

#pragma unroll
    for (int mt = 0; mt < 4; mt++)
#pragma unroll
        for (int nt = 0; nt < 8; nt++) {
            const int row = mBase + wm + mt * 16 + lg;
            const int col = nl0 + wn + nt * 8 + 2 * t4;
            *(float2*)&C[(size_t)row * cN + col] =
                make_float2(acc[mt][nt][0], acc[mt][nt][1]);
            *(float2*)&C[(size_t)(row + 8) * cN + col] =
                make_float2(acc[mt][nt][2], acc[mt][nt][3]);
        }
}

// ---------------------------------------------------------------------------
// Register-resident flash attention. Br=128, Bc=64, 8 warps.
// Phase-A K fragments via ldmatrix.x4; softmax in registers (quad shfl).
// ---------------------------------------------------------------------------
#define BQ 128
#define BK 64
#define LDK 132
#define LDV 136
#define LDQS 132
#define ATTN_SMEM_FLOATS (BK * LDK + BK * LDV)

__global__ __launch_bounds__(256, 1) void attn_mma(const float* __restrict__ q,
                                                   const float* __restrict__ k,
                                                   const float* __restrict__ v,
                                                   float* __restrict__ out) {
    extern __shared__ float sm[];
    float* Ks = sm;                 // [BK][LDK]
    float* Vs = sm + BK * LDK;      // [BK][LDV]
    float* Qstage = sm;             // [BQ][LDQS] overlay (pre-loop only)

    const int tid = threadIdx.x;
    const int w = tid >> 5;
    const int lane = tid & 31;
    const int lg = lane >> 2;
    const int t4 = lane & 3;

    const int qt = gridDim.x - 1 - blockIdx.x;   // heavy tiles first
    const int h = blockIdx.y;
    const int b = blockIdx.z;
    const int grp = h / (HEADS / GROUPS);
    const int qBase = qt * BQ;
    const int wq0 = w * 16;

    const float qscale = 0.08838834764831845f * 1.4426950408889634f;

    // ---- stage Q (scaled + tf32) then pull fragments to registers ----
#pragma unroll
    for (int rnd = 0; rnd < 16; rnd++) {
        const int row = (tid >> 5) + rnd * 8;
        const float* qp = q + (size_t)(b * SEQ + qBase + row) * DM + h * HD +
                          lane * 4;
        float4 val = *(const float4*)qp;
        *(float4*)&Qstage[row * LDQS + lane * 4] =
            make_float4(__uint_as_float(f2tf(val.x * qscale)),
                        __uint_as_float(f2tf(val.y * qscale)),
                        __uint_as_float(f2tf(val.z * qscale)),
                        __uint_as_float(f2tf(val.w * qscale)));
    }
    __syncthreads();

    unsigned qf[16][4];
    {
        const int qRow = wq0 + ((lane >> 3) & 1) * 8 + (lane & 7);
        const int qCol = (lane >> 4) * 4;
#pragma unroll
        for (int ks = 0; ks < 16; ks++)
            ldmx4(qf[ks], &Qstage[qRow * LDQS + ks * 8 + qCol]);
    }

    float oacc[16][4];
#pragma unroll
    for (int nt = 0; nt < 16; nt++)
#pragma unroll
        for (int i = 0; i < 4; i++) oacc[nt][i] = 0.f;

    float m0 = -1e30f, m1 = -1e30f, l0 = 0.f, l1 = 0.f;
    const int lastRow = qBase + wq0 + 15;
    const int row0g = qBase + wq0 + lg;
    const int nkt = (qBase + BQ) / BK;

    // phase-A ldmatrix address pieces
    const int kRow = ((lane >> 4) & 1) * 8 + (lane & 7);
    const int kCol = ((lane >> 3) & 1) * 4;

    for (int kt = 0; kt < nkt; kt++) {
        const int kBase = kt * BK;
        __syncthreads();

        // ---- cooperative K/V tile load (fp32 -> tf32 bits) ----
#pragma unroll
        for (int rnd = 0; rnd < 8; rnd++) {
            const int row = (tid >> 5) + rnd * 8;
            const size_t base = (size_t)(b * SEQ + kBase + row) * DKV +
                                grp * HD + lane * 4;
            float4 kv4 = *(const float4*)(k + base);
            *(float4*)&Ks[row * LDK + lane * 4] =
                make_float4(__uint_as_float(f2tf(kv4.x)), __uint_as_float(f2tf(kv4.y)),
                            __uint_as_float(f2tf(kv4.z)), __uint_as_float(f2tf(kv4.w)));
            float4 vv4 = *(const float4*)(v + base);
            *(float4*)&Vs[row * LDV + lane * 4] =
                make_float4(__uint_as_float(f2tf(vv4.x)), __uint_as_float(f2tf(vv4.y)),
                            __uint_as_float(f2tf(vv4.z)), __uint_as_float(f2tf(vv4.w)));
        }
        __syncthreads();

        if (kBase > lastRow) continue;   // warp-uniform; barrier counts match

        // ---- phase A: S = Q K^T (ldmatrix B-frags) ----
        float sacc[8][4];
#pragma unroll
        for (int nt = 0; nt < 8; nt++)
#pragma unroll
            for (int i = 0; i < 4; i++) sacc[nt][i] = 0.f;

#pragma unroll
        for (int ks = 0; ks < 16; ks++) {
            const int k0 = ks * 8;
#pragma unroll
            for (int ntp = 0; ntp < 4; ntp++) {
                unsigned bq[4];
                ldmx4(bq, &Ks[(ntp * 16 + kRow) * LDK + k0 + kCol]);
                mma8(sacc[2 * ntp], qf[ks], bq);
                mma8(sacc[2 * ntp + 1], qf[ks], bq + 2);
            }
        }

        // ---- causal mask ----
        if (kBase + BK - 1 > qBase + wq0) {
#pragma unroll
            for (int nt = 0; nt < 8; nt++) {
                const int c0 = kBase + nt * 8 + 2 * t4;
                if (c0 > row0g) sacc[nt][0] = -1e30f;
                if (c0 + 1 > row0g) sacc[nt][1] = -1e30f;
                if (c0 > row0g + 8) sacc[nt][2] = -1e30f;
                if (c0 + 1 > row0g + 8) sacc[nt][3] = -1e30f;
            }
        }

        // ---- online softmax (base-2), registers + quad shfl ----
        float mx0 = -1e30f, mx1 = -1e30f;
#pragma unroll
        for (int nt = 0; nt < 8; nt++) {
            mx0 = fmaxf(mx0, fmaxf(sacc[nt][0], sacc[nt][1]));
            mx1 = fmaxf(mx1, fmaxf(sacc[nt][2], sacc[nt][3]));
        }
        mx0 = fmaxf(mx0, __shfl_xor_sync(0xffffffff, mx0, 1));
        mx0 = fmaxf(mx0, __shfl_xor_sync(0xffffffff, mx0, 2));
        mx1 = fmaxf(mx1, __shfl_xor_sync(0xffffffff, mx1, 1));
        mx1 = fmaxf(mx1, __shfl_xor_sync(0xffffffff, mx1, 2));

        const float mn0 = fmaxf(m0, mx0);
        const float mn1 = fmaxf(m1, mx1);
        const float sc0 = fexp2(m0 - mn0);
        const float sc1 = fexp2(m1 - mn1);

        float sum0 = 0.f, sum1 = 0.f;
#pragma unroll
        for (int nt = 0; nt < 8; nt++) {
            float p0 = fexp2(sacc[nt][0] - mn0);
            float p1 = fexp2(sacc[nt][1] - mn0);
            float p2 = fexp2(sacc[nt][2] - mn1);
            float p3 = fexp2(sacc[nt][3] - mn1);
            sacc[nt][0] = p0; sacc[nt][1] = p1;
            sacc[nt][2] = p2; sacc[nt][3] = p3;
            sum0 += p0 + p1;
            sum1 += p2 + p3;
        }
        sum0 += __shfl_xor_sync(0xffffffff, sum0, 1);
        sum0 += __shfl_xor_sync(0xffffffff, sum0, 2);
        sum1 += __shfl_xor_sync(0xffffffff, sum1, 1);
        sum1 += __shfl_xor_sync(0xffffffff, sum1, 2);

        l0 = l0 * sc0 + sum0;  m0 = mn0;
        l1 = l1 * sc1 + sum1;  m1 = mn1;

#pragma unroll
        for (int nt = 0; nt < 16; nt++) {
            oacc[nt][0] *= sc0;
            oacc[nt][1] *= sc0;
            oacc[nt][2] *= sc1;
            oacc[nt][3] *= sc1;
        }

        // ---- phase C: O += P V ; P re-shaped C-frag -> A-frag via shfl ----
        const int srcA = (lane & 28) | (t4 >> 1);
        const int srcB = srcA + 2;
        const bool odd = (t4 & 1);
#pragma unroll
        for (int ks = 0; ks < 8; ks++) {
            const float v0 = sacc[ks][0], v1 = sacc[ks][1];
            const float v2 = sacc[ks][2], v3 = sacc[ks][3];
            float x0 = __shfl_sync(0xffffffff, v0, srcA);
            float x1 = __shfl_sync(0xffffffff, v1, srcA);
            float y0 = __shfl_sync(0xffffffff, v0, srcB);
            float y1 = __shfl_sync(0xffffffff, v1, srcB);
            float z0 = __shfl_sync(0xffffffff, v2, srcA);
            float z1 = __shfl_sync(0xffffffff, v3, srcA);
            float u0 = __shfl_sync(0xffffffff, v2, srcB);
            float u1 = __shfl_sync(0xffffffff, v3, srcB);
            unsigned pf[4];
            pf[0] = f2tf(odd ? x1 : x0);
            pf[1] = f2tf(odd ? z1 : z0);
            pf[2] = f2tf(odd ? y1 : y0);
            pf[3] = f2tf(odd ? u1 : u0);

            const int k0 = ks * 8;
#pragma unroll
            for (int nt = 0; nt < 16; nt++) {
                unsigned bf[2];
                bf[0] = __float_as_uint(Vs[(k0 + t4) * LDV + nt * 8 + lg]);
                bf[1] = __float_as_uint(Vs[(k0 + t4 + 4) * LDV + nt * 8 + lg]);
                mma8(oacc[nt], pf, bf);
            }
        }
    }

    // ---- finalize + write ----
    const float inv0 = 1.0f / l0;
    const float inv1 = 1.0f / l1;
#pragma unroll
    for (int nt = 0; nt < 16; nt++) {
        const int d = h * HD + nt * 8 + 2 * t4;
        *(float2*)&out[(size_t)(b * SEQ + row0g) * DM + d] =
            make_float2(oacc[nt][0] * inv0, oacc[nt][1] * inv0);
        *(float2*)&out[(size_t)(b * SEQ + row0g + 8) * DM + d] =
            make_float2(oacc[nt][2] * inv1, oacc[nt][3] * inv1);
    }
}

// ---------------------------------------------------------------------------
extern "C" void kernel_launch(void* const* d_in, const int* in_sizes, int n_in,
                              void* d_out, int out_size) {
    const float* x = (const float*)d_in[0];
    const float* Wq = (const float*)d_in[1];
    const float* Wk = (const float*)d_in[2];
    const float* Wv = (const float*)d_in[3];
    float* out = (float*)d_out;

    float *pq = nullptr, *pk = nullptr, *pv = nullptr;
    cudaGetSymbolAddress((void**)&pq, g_q);
    cudaGetSymbolAddress((void**)&pk, g_k);
    cudaGetSymbolAddress((void**)&pv, g_v);

    static const size_t gemmSmem = GEMM_SMEM_FLOATS * sizeof(float);
    cudaFuncSetAttribute(gemm_qkv, cudaFuncAttributeMaxDynamicSharedMemorySize,
                         (int)gemmSmem);
    dim3 thr(256);
    dim3 gg(12, 32);   // 12 n-tiles (8 Q + 2 K + 2 V) x 32 m-tiles
    gemm_qkv<<<gg, thr, gemmSmem>>>(x, Wq, Wk, Wv);

    static const size_t attnSmem = ATTN_SMEM_FLOATS * sizeof(float);
    cudaFuncSetAttribute(attn_mma, cudaFuncAttributeMaxDynamicSharedMemorySize,
                         (int)attnSmem);
    dim3 ga(SEQ / BQ, HEADS, BATCH);
    attn_mma<<<ga, thr, attnSmem>>>(pq, pk, pv, out);
}